// round 2
// baseline (speedup 1.0000x reference)
#include <cuda_runtime.h>
#include <math.h>

#define B_SZ   16384
#define NTAB   26
#define VOCAB  100000
#define EMB_D  64

// ---------------- scratch (device globals; no allocation allowed) ----------
__device__ float g_x1[B_SZ * 512];          // bot layer0 out
__device__ float g_x2[B_SZ * 256];          // bot layer1 out
__device__ float g_T [B_SZ * 27 * 64];      // Tmat: row0 = bot out, rows 1..26 = emb sums
__device__ float g_R [B_SZ * 416];          // interaction out (415 + 1 zero pad)
__device__ float g_z1[B_SZ * 512];          // top layer0 out
__device__ float g_z2[B_SZ * 256];          // top layer1 out
__device__ float g_W0pad[512 * 416];        // top_W0 padded K 415->416
__device__ int   g_idx_is64;                // 1 if lS_i is int64, 0 if int32

// ---------------- detect index dtype ---------------------------------------
// If lS_i is int64 (values < 2^31), every odd 32-bit word (high half) is 0.
// If int32, odd words are random indices in [0,100000) -> almost surely nonzero.
__global__ void detect_idx_kernel(const int* __restrict__ lsi32)
{
    int any = 0;
    for (int k = threadIdx.x; k < 2048; k += 32)
        if (lsi32[2 * k + 1] != 0) any = 1;
    any = __any_sync(0xFFFFFFFFu, any);
    if (threadIdx.x == 0) g_idx_is64 = any ? 0 : 1;
}

// ---------------- bot layer 0: [B,13] @ W[512,13]^T + b, relu --------------
__global__ void __launch_bounds__(256) bot0_kernel(
    const float* __restrict__ X, const float* __restrict__ W,
    const float* __restrict__ bias, float* __restrict__ Y)
{
    __shared__ float sW[512 * 13];
    __shared__ float sb[512];
    __shared__ float sx[16 * 13];
    const int tid = threadIdx.x;
    const int r0 = blockIdx.x * 16;
    for (int i = tid; i < 512 * 13; i += 256) sW[i] = W[i];
    for (int i = tid; i < 512; i += 256) sb[i] = bias[i];
    for (int i = tid; i < 16 * 13; i += 256) sx[i] = X[r0 * 13 + i];
    __syncthreads();
    for (int o = tid; o < 16 * 512; o += 256) {
        const int r = o >> 9;
        const int c = o & 511;
        float acc = sb[c];
        #pragma unroll
        for (int k = 0; k < 13; k++) acc += sx[r * 13 + k] * sW[c * 13 + k];
        Y[(size_t)(r0 + r) * 512 + c] = fmaxf(acc, 0.f);
    }
}

// ---------------- generic tiled GEMM: C = act(A[M,K] @ W[N,K]^T + bias) ----
// BM=128, BN=64, BK=16, 256 threads, 8x4 per thread. M%128==0, N%64==0, K%16==0.
__global__ void __launch_bounds__(256) gemm_kernel(
    const float* __restrict__ A, int lda,
    const float* __restrict__ W,        // [N,K] row-major, leading dim K
    const float* __restrict__ bias,
    float* __restrict__ C, int ldc,
    int K, int relu)
{
    const int BM = 128, BN = 64, BK = 16;
    __shared__ float As[BK][BM];
    __shared__ float Ws[BK][BN];

    const int tid = threadIdx.x;
    const int m0 = blockIdx.y * BM;
    const int n0 = blockIdx.x * BN;
    const int tx = tid & 15;   // 16 cols of threads -> 4 outputs each
    const int ty = tid >> 4;   // 16 rows of threads -> 8 outputs each

    float acc[8][4];
    #pragma unroll
    for (int i = 0; i < 8; i++)
        #pragma unroll
        for (int j = 0; j < 4; j++) acc[i][j] = 0.f;

    const float* Aptr = A + (size_t)m0 * lda;
    const float* Wptr = W + (size_t)n0 * K;

    for (int k0 = 0; k0 < K; k0 += BK) {
        // load A tile 128x16 (2 float4 per thread), transposed into As[k][m]
        #pragma unroll
        for (int r = 0; r < 2; r++) {
            const int idx = tid + r * 256;      // 0..511
            const int row = idx >> 2;           // 0..127
            const int kq  = (idx & 3) * 4;      // 0,4,8,12
            float4 v = *reinterpret_cast<const float4*>(Aptr + (size_t)row * lda + k0 + kq);
            As[kq + 0][row] = v.x; As[kq + 1][row] = v.y;
            As[kq + 2][row] = v.z; As[kq + 3][row] = v.w;
        }
        // load W tile 64x16 (1 float4 per thread), transposed into Ws[k][n]
        {
            const int row = tid >> 2;           // 0..63
            const int kq  = (tid & 3) * 4;
            float4 v = *reinterpret_cast<const float4*>(Wptr + (size_t)row * K + k0 + kq);
            Ws[kq + 0][row] = v.x; Ws[kq + 1][row] = v.y;
            Ws[kq + 2][row] = v.z; Ws[kq + 3][row] = v.w;
        }
        __syncthreads();

        #pragma unroll
        for (int kk = 0; kk < BK; kk++) {
            float a[8], b[4];
            #pragma unroll
            for (int i = 0; i < 8; i++) a[i] = As[kk][ty * 8 + i];
            #pragma unroll
            for (int j = 0; j < 4; j++) b[j] = Ws[kk][tx * 4 + j];
            #pragma unroll
            for (int i = 0; i < 8; i++)
                #pragma unroll
                for (int j = 0; j < 4; j++) acc[i][j] += a[i] * b[j];
        }
        __syncthreads();
    }

    float bv[4];
    #pragma unroll
    for (int j = 0; j < 4; j++) bv[j] = bias[n0 + tx * 4 + j];
    #pragma unroll
    for (int i = 0; i < 8; i++) {
        const int m = m0 + ty * 8 + i;
        #pragma unroll
        for (int j = 0; j < 4; j++) {
            float v = acc[i][j] + bv[j];
            if (relu) v = fmaxf(v, 0.f);
            C[(size_t)m * ldc + n0 + tx * 4 + j] = v;
        }
    }
}

// ---------------- embedding gather: one warp per (table, batch) ------------
__global__ void __launch_bounds__(256) gather_kernel(
    const float* __restrict__ emb, const void* __restrict__ lsi,
    float* __restrict__ T)
{
    const int gid = blockIdx.x * 8 + (threadIdx.x >> 5);
    const int lane = threadIdx.x & 31;
    if (gid >= NTAB * B_SZ) return;
    const int t = gid / B_SZ;
    const int b = gid - t * B_SZ;
    const int is64 = g_idx_is64;
    const size_t base = ((size_t)t * B_SZ + b) * 4;
    const long long* ip64 = (const long long*)lsi;
    const int*       ip32 = (const int*)lsi;
    float2 acc = make_float2(0.f, 0.f);
    #pragma unroll
    for (int l = 0; l < 4; l++) {
        long long ix = is64 ? ip64[base + l] : (long long)ip32[base + l];
        if (ix < 0) ix = 0;
        if (ix >= VOCAB) ix = VOCAB - 1;
        const float2* row = reinterpret_cast<const float2*>(
            emb + ((size_t)t * VOCAB + (size_t)ix) * EMB_D);
        float2 v = __ldg(&row[lane]);
        acc.x += v.x; acc.y += v.y;
    }
    reinterpret_cast<float2*>(T + ((size_t)b * 27 + 1 + t) * EMB_D)[lane] = acc;
}

// ---------------- interaction: lower-tri pairwise dots ---------------------
__global__ void __launch_bounds__(128) interact_kernel(
    const float* __restrict__ T, float* __restrict__ R)
{
    __shared__ float s[27][65];   // pad to kill bank conflicts
    const int b = blockIdx.x;
    const int tid = threadIdx.x;
    const float* Tb = T + (size_t)b * 1728;
    for (int i = tid; i < 1728; i += 128) s[i >> 6][i & 63] = Tb[i];
    __syncthreads();
    float* Rb = R + (size_t)b * 416;
    if (tid < 64) Rb[tid] = s[0][tid];
    if (tid == 127) Rb[415] = 0.f;
    for (int p = tid; p < 351; p += 128) {
        int i = (int)(0.5f * (1.0f + sqrtf(8.0f * (float)p + 1.0f)));
        while ((i * (i - 1)) / 2 > p) --i;
        while (((i + 1) * i) / 2 <= p) ++i;
        const int j = p - (i * (i - 1)) / 2;
        const float* si = s[i];
        const float* sj = s[j];
        float acc = 0.f;
        #pragma unroll
        for (int k = 0; k < 64; k++) acc += si[k] * sj[k];
        Rb[64 + p] = acc;
    }
}

// ---------------- pad top_W0 K: 415 -> 416 --------------------------------
__global__ void padW_kernel(const float* __restrict__ W, float* __restrict__ Wp)
{
    const int i = blockIdx.x * 256 + threadIdx.x;
    if (i >= 512 * 416) return;
    const int n = i / 416;
    const int k = i - n * 416;
    Wp[i] = (k < 415) ? W[n * 415 + k] : 0.f;
}

// ---------------- final: [B,256] @ W[1,256]^T + b, sigmoid -----------------
__global__ void __launch_bounds__(256) top_final_kernel(
    const float* __restrict__ Z, const float* __restrict__ W,
    const float* __restrict__ bias, float* __restrict__ out)
{
    const int b = blockIdx.x * 8 + (threadIdx.x >> 5);
    const int lane = threadIdx.x & 31;
    const float* zr = Z + (size_t)b * 256;
    float acc = 0.f;
    #pragma unroll
    for (int k = lane; k < 256; k += 32) acc += zr[k] * W[k];
    #pragma unroll
    for (int off = 16; off > 0; off >>= 1)
        acc += __shfl_xor_sync(0xFFFFFFFFu, acc, off);
    if (lane == 0) {
        const float v = acc + bias[0];
        out[b] = 1.f / (1.f + expf(-v));
    }
}

// ---------------- launch ----------------------------------------------------
extern "C" void kernel_launch(void* const* d_in, const int* in_sizes, int n_in,
                              void* d_out, int out_size)
{
    (void)n_in; (void)out_size;
    const float* dense_x = (const float*)d_in[0];
    const void*  lsi     = d_in[2];
    const float* emb     = (const float*)d_in[3];

    const float *bW0, *bb0, *bW1, *bb1, *bW2, *bb2;
    const float *tW0, *tb0, *tW1, *tb1, *tW2, *tb2;
    if (in_sizes[6] == 512 * 415) {
        // setup_inputs dict order: bot_W0,bot_b0,top_W0,top_b0,bot_W1,...
        bW0 = (const float*)d_in[4];  bb0 = (const float*)d_in[5];
        tW0 = (const float*)d_in[6];  tb0 = (const float*)d_in[7];
        bW1 = (const float*)d_in[8];  bb1 = (const float*)d_in[9];
        tW1 = (const float*)d_in[10]; tb1 = (const float*)d_in[11];
        bW2 = (const float*)d_in[12]; bb2 = (const float*)d_in[13];
        tW2 = (const float*)d_in[14]; tb2 = (const float*)d_in[15];
    } else {
        // reference-signature order: all bot then all top
        bW0 = (const float*)d_in[4];  bb0 = (const float*)d_in[5];
        bW1 = (const float*)d_in[6];  bb1 = (const float*)d_in[7];
        bW2 = (const float*)d_in[8];  bb2 = (const float*)d_in[9];
        tW0 = (const float*)d_in[10]; tb0 = (const float*)d_in[11];
        tW1 = (const float*)d_in[12]; tb1 = (const float*)d_in[13];
        tW2 = (const float*)d_in[14]; tb2 = (const float*)d_in[15];
    }

    float *x1, *x2, *T, *R, *z1, *z2, *W0p;
    cudaGetSymbolAddress((void**)&x1,  g_x1);
    cudaGetSymbolAddress((void**)&x2,  g_x2);
    cudaGetSymbolAddress((void**)&T,   g_T);
    cudaGetSymbolAddress((void**)&R,   g_R);
    cudaGetSymbolAddress((void**)&z1,  g_z1);
    cudaGetSymbolAddress((void**)&z2,  g_z2);
    cudaGetSymbolAddress((void**)&W0p, g_W0pad);

    // detect int32 vs int64 index layout (writes g_idx_is64)
    detect_idx_kernel<<<1, 32>>>((const int*)lsi);

    // prep: pad top_W0 to K=416
    padW_kernel<<<(512 * 416 + 255) / 256, 256>>>(tW0, W0p);

    // bottom MLP
    bot0_kernel<<<B_SZ / 16, 256>>>(dense_x, bW0, bb0, x1);
    gemm_kernel<<<dim3(256 / 64, B_SZ / 128), 256>>>(x1, 512, bW1, bb1, x2, 256, 512, 1);
    gemm_kernel<<<dim3(64 / 64,  B_SZ / 128), 256>>>(x2, 256, bW2, bb2, T, 1728, 256, 1);

    // embedding gather-sum into Tmat rows 1..26
    gather_kernel<<<(NTAB * B_SZ) / 8, 256>>>(emb, lsi, T);

    // interaction -> R[B,416]
    interact_kernel<<<B_SZ, 128>>>(T, R);

    // top MLP
    gemm_kernel<<<dim3(512 / 64, B_SZ / 128), 256>>>(R,  416, W0p, tb0, z1, 512, 416, 1);
    gemm_kernel<<<dim3(256 / 64, B_SZ / 128), 256>>>(z1, 512, tW1, tb1, z2, 256, 512, 1);
    top_final_kernel<<<B_SZ / 8, 256>>>(z2, tW2, tb2, (float*)d_out);
}

// round 4
// speedup vs baseline: 1.8498x; 1.8498x over previous
#include <cuda_runtime.h>
#include <cuda_bf16.h>
#include <math.h>
#include <stdint.h>

#define B_SZ   16384
#define NTAB   26
#define VOCAB  100000
#define EMB_D  64

// ======================= scratch (device globals) ==========================
__device__ __align__(256) float g_T [B_SZ * 27 * 64];      // Tmat fp32
__device__ __align__(256) float g_z2[B_SZ * 256];           // top L1 out fp32

__device__ __align__(256) __nv_bfloat16 g_x1h[B_SZ * 512];
__device__ __align__(256) __nv_bfloat16 g_x1l[B_SZ * 512];
__device__ __align__(256) __nv_bfloat16 g_x2h[B_SZ * 256];
__device__ __align__(256) __nv_bfloat16 g_x2l[B_SZ * 256];
__device__ __align__(256) __nv_bfloat16 g_Rh [B_SZ * 448];
__device__ __align__(256) __nv_bfloat16 g_Rl [B_SZ * 448];
__device__ __align__(256) __nv_bfloat16 g_z1h[B_SZ * 512];
__device__ __align__(256) __nv_bfloat16 g_z1l[B_SZ * 512];

__device__ __align__(256) __nv_bfloat16 g_bW1h[256 * 512];
__device__ __align__(256) __nv_bfloat16 g_bW1l[256 * 512];
__device__ __align__(256) __nv_bfloat16 g_bW2h[64 * 256];
__device__ __align__(256) __nv_bfloat16 g_bW2l[64 * 256];
__device__ __align__(256) __nv_bfloat16 g_tW0h[512 * 448];
__device__ __align__(256) __nv_bfloat16 g_tW0l[512 * 448];
__device__ __align__(256) __nv_bfloat16 g_tW1h[256 * 512];
__device__ __align__(256) __nv_bfloat16 g_tW1l[256 * 512];

__device__ int g_idx_is64;

// ======================= helpers ============================================
__device__ __forceinline__ uint32_t smem_u32(const void* p) {
    uint32_t a;
    asm("{ .reg .u64 t; cvta.to.shared.u64 t, %1; cvt.u32.u64 %0, t; }"
        : "=r"(a) : "l"(p));
    return a;
}
__device__ __forceinline__ void cpa16(uint32_t saddr, const void* g) {
    asm volatile("cp.async.cg.shared.global [%0], [%1], 16;" :: "r"(saddr), "l"(g));
}
__device__ __forceinline__ void cpa_commit() {
    asm volatile("cp.async.commit_group;" ::: "memory");
}
__device__ __forceinline__ void cpa_wait1() {
    asm volatile("cp.async.wait_group 1;" ::: "memory");
}
__device__ __forceinline__ void cpa_wait0() {
    asm volatile("cp.async.wait_group 0;" ::: "memory");
}
__device__ __forceinline__ void ldm_x4(uint32_t a, uint32_t& r0, uint32_t& r1,
                                       uint32_t& r2, uint32_t& r3) {
    asm volatile("ldmatrix.sync.aligned.m8n8.x4.shared.b16 {%0,%1,%2,%3}, [%4];"
                 : "=r"(r0), "=r"(r1), "=r"(r2), "=r"(r3) : "r"(a));
}
__device__ __forceinline__ void mma16816(float* c, const uint32_t* a,
                                         const uint32_t* b) {
    asm volatile(
        "mma.sync.aligned.m16n8k16.row.col.f32.bf16.bf16.f32 "
        "{%0,%1,%2,%3}, {%4,%5,%6,%7}, {%8,%9}, {%0,%1,%2,%3};"
        : "+f"(c[0]), "+f"(c[1]), "+f"(c[2]), "+f"(c[3])
        : "r"(a[0]), "r"(a[1]), "r"(a[2]), "r"(a[3]), "r"(b[0]), "r"(b[1]));
}
__device__ __forceinline__ void split_f32(float v, __nv_bfloat16& h, __nv_bfloat16& l) {
    h = __float2bfloat16(v);
    l = __float2bfloat16(v - __bfloat162float(h));
}

// ======================= index dtype detect =================================
__global__ void detect_idx_kernel(const int* __restrict__ lsi32) {
    int any = 0;
    for (int k = threadIdx.x; k < 2048; k += 32)
        if (lsi32[2 * k + 1] != 0) any = 1;
    any = __any_sync(0xFFFFFFFFu, any);
    if (threadIdx.x == 0) g_idx_is64 = any ? 0 : 1;
}

// ======================= weight pad + split =================================
__global__ void padsplit_kernel(const float* __restrict__ W,
                                __nv_bfloat16* __restrict__ Wh,
                                __nv_bfloat16* __restrict__ Wl,
                                int N, int Kin, int Kpad) {
    const int i = blockIdx.x * 256 + threadIdx.x;
    if (i >= N * Kpad) return;
    const int n = i / Kpad;
    const int k = i - n * Kpad;
    const float v = (k < Kin) ? W[n * Kin + k] : 0.f;
    __nv_bfloat16 h, l; split_f32(v, h, l);
    Wh[i] = h; Wl[i] = l;
}

// ======================= bot layer 0 (K=13) -> split out ====================
__global__ void __launch_bounds__(256) bot0_kernel(
    const float* __restrict__ X, const float* __restrict__ W,
    const float* __restrict__ bias,
    __nv_bfloat16* __restrict__ Yh, __nv_bfloat16* __restrict__ Yl)
{
    __shared__ float sW[512 * 13];
    __shared__ float sb[512];
    __shared__ float sx[16 * 13];
    const int tid = threadIdx.x;
    const int r0 = blockIdx.x * 16;
    for (int i = tid; i < 512 * 13; i += 256) sW[i] = W[i];
    for (int i = tid; i < 512; i += 256) sb[i] = bias[i];
    for (int i = tid; i < 16 * 13; i += 256) sx[i] = X[r0 * 13 + i];
    __syncthreads();
    for (int o = tid; o < 16 * 512; o += 256) {
        const int r = o >> 9;
        const int c = o & 511;
        float acc = sb[c];
        #pragma unroll
        for (int k = 0; k < 13; k++) acc += sx[r * 13 + k] * sW[c * 13 + k];
        acc = fmaxf(acc, 0.f);
        __nv_bfloat16 h, l; split_f32(acc, h, l);
        const size_t idx = (size_t)(r0 + r) * 512 + c;
        Yh[idx] = h; Yl[idx] = l;
    }
}

// ======================= mma.sync bf16x3 GEMM ===============================
// C[M,N] = act(A[M,K] @ W[N,K]^T + bias). A/W pre-split hi/lo bf16.
// CTA tile 128x64, BK=64 bf16 (128B rows, XOR swizzle), double-buffered
// cp.async. 8 warps in 4(M) x 2(N); 32x32 per warp via m16n8k16.
// Stage layout (49152 B): Ah @0 (16K), Al @16K, Wh @32K (8K), Wl @40K.
#define STG 49152u
__device__ __forceinline__ uint32_t swz(int row, int chunk) {
    return (uint32_t)(row * 128 + ((chunk ^ (row & 7)) * 16));
}

__global__ void __launch_bounds__(256) gemm_mma(
    const __nv_bfloat16* __restrict__ Ah, const __nv_bfloat16* __restrict__ Al,
    const __nv_bfloat16* __restrict__ Wh, const __nv_bfloat16* __restrict__ Wl,
    const float* __restrict__ bias, int K, int NC,
    float* __restrict__ Cf,
    __nv_bfloat16* __restrict__ Ch, __nv_bfloat16* __restrict__ Cl,
    int ldc, int relu, int splitOut)
{
    extern __shared__ char smem[];
    const uint32_t sb = smem_u32(smem);
    const int tid  = threadIdx.x;
    const int lane = tid & 31;
    const int wid  = tid >> 5;
    const int wm   = wid >> 1;       // 0..3  (M)
    const int wn   = wid & 1;        // 0..1  (N)
    const int m0 = blockIdx.y * 128;
    const int n0 = blockIdx.x * 64;
    const size_t rowB = (size_t)K * 2;

    const char* gAh = (const char*)Ah + (size_t)m0 * rowB;
    const char* gAl = (const char*)Al + (size_t)m0 * rowB;
    const char* gWh = (const char*)Wh + (size_t)n0 * rowB;
    const char* gWl = (const char*)Wl + (size_t)n0 * rowB;

    float acc[2][4][4];
    #pragma unroll
    for (int t = 0; t < 2; t++)
        #pragma unroll
        for (int u = 0; u < 4; u++)
            #pragma unroll
            for (int v = 0; v < 4; v++) acc[t][u][v] = 0.f;

    // ---- stage loader: 12 cp.async x 16B per thread --------------------
    auto load_stage = [&](int c) {
        const uint32_t so = sb + (uint32_t)(c & 1) * STG;
        const size_t kb = (size_t)c * 128;
        #pragma unroll
        for (int i = 0; i < 4; i++) {
            const int e = tid + i * 256;            // 0..1023
            const int row = e >> 3;                 // 0..127
            const int ch  = e & 7;                  // 0..7
            const size_t gs = (size_t)row * rowB + kb + ch * 16;
            const uint32_t d = swz(row, ch);
            cpa16(so + d,          gAh + gs);
            cpa16(so + 16384 + d,  gAl + gs);
        }
        #pragma unroll
        for (int i = 0; i < 2; i++) {
            const int e = tid + i * 256;            // 0..511
            const int row = e >> 3;                 // 0..63
            const int ch  = e & 7;
            const size_t gs = (size_t)row * rowB + kb + ch * 16;
            const uint32_t d = swz(row, ch);
            cpa16(so + 32768 + d, gWh + gs);
            cpa16(so + 40960 + d, gWl + gs);
        }
        cpa_commit();
    };

    load_stage(0);
    for (int c = 0; c < NC; ++c) {
        if (c + 1 < NC) load_stage(c + 1);
        if (c + 1 < NC) cpa_wait1(); else cpa_wait0();
        __syncthreads();

        const uint32_t so = sb + (uint32_t)(c & 1) * STG;
        const uint32_t sAhB = so, sAlB = so + 16384;
        const uint32_t sWhB = so + 32768, sWlB = so + 40960;

        #pragma unroll
        for (int kk = 0; kk < 4; kk++) {
            uint32_t ah[2][4], al[2][4], bh[8], bl[8];
            // A fragments: 2 m-tiles x (hi,lo)
            #pragma unroll
            for (int t = 0; t < 2; t++) {
                const int row = wm * 32 + t * 16 + (lane & 15);
                const int ch  = kk * 2 + (lane >> 4);
                const uint32_t d = swz(row, ch);
                ldm_x4(sAhB + d, ah[t][0], ah[t][1], ah[t][2], ah[t][3]);
                ldm_x4(sAlB + d, al[t][0], al[t][1], al[t][2], al[t][3]);
            }
            // B fragments: 2 pairs (4 n-tiles) x (hi,lo)
            #pragma unroll
            for (int p = 0; p < 2; p++) {
                const int row = wn * 32 + p * 16 + ((lane >> 4) & 1) * 8 + (lane & 7);
                const int ch  = kk * 2 + ((lane >> 3) & 1);
                const uint32_t d = swz(row, ch);
                ldm_x4(sWhB + d, bh[p * 4 + 0], bh[p * 4 + 1], bh[p * 4 + 2], bh[p * 4 + 3]);
                ldm_x4(sWlB + d, bl[p * 4 + 0], bl[p * 4 + 1], bl[p * 4 + 2], bl[p * 4 + 3]);
            }
            // 24 MMAs: 3 terms x 2 m-tiles x 4 n-tiles
            #pragma unroll
            for (int t = 0; t < 2; t++)
                #pragma unroll
                for (int u = 0; u < 4; u++) {
                    mma16816(acc[t][u], ah[t], &bh[u * 2]);
                    mma16816(acc[t][u], ah[t], &bl[u * 2]);
                    mma16816(acc[t][u], al[t], &bh[u * 2]);
                }
        }
        __syncthreads();
    }

    // ---- epilogue: bias + relu, write split-bf16 or fp32 ---------------
    #pragma unroll
    for (int t = 0; t < 2; t++) {
        const int rbase = m0 + wm * 32 + t * 16 + (lane >> 2);
        #pragma unroll
        for (int u = 0; u < 4; u++) {
            const int gn = n0 + wn * 32 + u * 8 + (lane & 3) * 2;
            const float b0 = __ldg(&bias[gn]);
            const float b1 = __ldg(&bias[gn + 1]);
            #pragma unroll
            for (int h = 0; h < 2; h++) {          // h=0: row, h=1: row+8
                float v0 = acc[t][u][h * 2 + 0] + b0;
                float v1 = acc[t][u][h * 2 + 1] + b1;
                if (relu) { v0 = fmaxf(v0, 0.f); v1 = fmaxf(v1, 0.f); }
                const size_t idx = (size_t)(rbase + h * 8) * ldc + gn;
                if (splitOut) {
                    __nv_bfloat16 h0, l0, h1, l1;
                    split_f32(v0, h0, l0); split_f32(v1, h1, l1);
                    *reinterpret_cast<__nv_bfloat162*>(Ch + idx) = __halves2bfloat162(h0, h1);
                    *reinterpret_cast<__nv_bfloat162*>(Cl + idx) = __halves2bfloat162(l0, l1);
                } else {
                    *reinterpret_cast<float2*>(Cf + idx) = make_float2(v0, v1);
                }
            }
        }
    }
}

// ======================= embedding gather ===================================
__global__ void __launch_bounds__(256) gather_kernel(
    const float* __restrict__ emb, const void* __restrict__ lsi,
    float* __restrict__ T)
{
    const int gid = blockIdx.x * 8 + (threadIdx.x >> 5);
    const int lane = threadIdx.x & 31;
    if (gid >= NTAB * B_SZ) return;
    const int t = gid / B_SZ;
    const int b = gid - t * B_SZ;
    const int is64 = g_idx_is64;
    const size_t base = ((size_t)t * B_SZ + b) * 4;
    const long long* ip64 = (const long long*)lsi;
    const int*       ip32 = (const int*)lsi;
    float2 acc = make_float2(0.f, 0.f);
    #pragma unroll
    for (int l = 0; l < 4; l++) {
        long long ix = is64 ? ip64[base + l] : (long long)ip32[base + l];
        if (ix < 0) ix = 0;
        if (ix >= VOCAB) ix = VOCAB - 1;
        const float2* row = reinterpret_cast<const float2*>(
            emb + ((size_t)t * VOCAB + (size_t)ix) * EMB_D);
        float2 v = __ldg(&row[lane]);
        acc.x += v.x; acc.y += v.y;
    }
    reinterpret_cast<float2*>(T + ((size_t)b * 27 + 1 + t) * EMB_D)[lane] = acc;
}

// ======================= interaction -> split R[B,448] ======================
__global__ void __launch_bounds__(128) interact_kernel(
    const float* __restrict__ T,
    __nv_bfloat16* __restrict__ Rh, __nv_bfloat16* __restrict__ Rl)
{
    __shared__ float s[27][65];
    const int b = blockIdx.x;
    const int tid = threadIdx.x;
    const float* Tb = T + (size_t)b * 1728;
    for (int i = tid; i < 1728; i += 128) s[i >> 6][i & 63] = Tb[i];
    __syncthreads();
    __nv_bfloat16* Rbh = Rh + (size_t)b * 448;
    __nv_bfloat16* Rbl = Rl + (size_t)b * 448;
    if (tid < 64) {
        __nv_bfloat16 h, l; split_f32(s[0][tid], h, l);
        Rbh[tid] = h; Rbl[tid] = l;
    }
    for (int c = 415 + tid; c < 448; c += 128) {
        Rbh[c] = __float2bfloat16(0.f); Rbl[c] = __float2bfloat16(0.f);
    }
    for (int p = tid; p < 351; p += 128) {
        int i = (int)(0.5f * (1.0f + sqrtf(8.0f * (float)p + 1.0f)));
        while ((i * (i - 1)) / 2 > p) --i;
        while (((i + 1) * i) / 2 <= p) ++i;
        const int j = p - (i * (i - 1)) / 2;
        const float* si = s[i];
        const float* sj = s[j];
        float acc = 0.f;
        #pragma unroll
        for (int k = 0; k < 64; k++) acc += si[k] * sj[k];
        __nv_bfloat16 h, l; split_f32(acc, h, l);
        Rbh[64 + p] = h; Rbl[64 + p] = l;
    }
}

// ======================= final layer + sigmoid ==============================
__global__ void __launch_bounds__(256) top_final_kernel(
    const float* __restrict__ Z, const float* __restrict__ W,
    const float* __restrict__ bias, float* __restrict__ out)
{
    const int b = blockIdx.x * 8 + (threadIdx.x >> 5);
    const int lane = threadIdx.x & 31;
    const float* zr = Z + (size_t)b * 256;
    float acc = 0.f;
    #pragma unroll
    for (int k = lane; k < 256; k += 32) acc += zr[k] * W[k];
    #pragma unroll
    for (int off = 16; off > 0; off >>= 1)
        acc += __shfl_xor_sync(0xFFFFFFFFu, acc, off);
    if (lane == 0) {
        const float v = acc + bias[0];
        out[b] = 1.f / (1.f + expf(-v));
    }
}

// ======================= launch =============================================
extern "C" void kernel_launch(void* const* d_in, const int* in_sizes, int n_in,
                              void* d_out, int out_size)
{
    (void)n_in; (void)out_size;
    const float* dense_x = (const float*)d_in[0];
    const void*  lsi     = d_in[2];
    const float* emb     = (const float*)d_in[3];

    const float *bW0, *bb0, *bW1, *bb1, *bW2, *bb2;
    const float *tW0, *tb0, *tW1, *tb1, *tW2, *tb2;
    if (in_sizes[6] == 512 * 415) {
        bW0 = (const float*)d_in[4];  bb0 = (const float*)d_in[5];
        tW0 = (const float*)d_in[6];  tb0 = (const float*)d_in[7];
        bW1 = (const float*)d_in[8];  bb1 = (const float*)d_in[9];
        tW1 = (const float*)d_in[10]; tb1 = (const float*)d_in[11];
        bW2 = (const float*)d_in[12]; bb2 = (const float*)d_in[13];
        tW2 = (const float*)d_in[14]; tb2 = (const float*)d_in[15];
    } else {
        bW0 = (const float*)d_in[4];  bb0 = (const float*)d_in[5];
        bW1 = (const float*)d_in[6];  bb1 = (const float*)d_in[7];
        bW2 = (const float*)d_in[8];  bb2 = (const float*)d_in[9];
        tW0 = (const float*)d_in[10]; tb0 = (const float*)d_in[11];
        tW1 = (const float*)d_in[12]; tb1 = (const float*)d_in[13];
        tW2 = (const float*)d_in[14]; tb2 = (const float*)d_in[15];
    }

    float *T, *z2;
    __nv_bfloat16 *x1h, *x1l, *x2h, *x2l, *Rh, *Rl, *z1h, *z1l;
    __nv_bfloat16 *bW1h, *bW1l, *bW2h, *bW2l, *tW0h, *tW0l, *tW1h, *tW1l;
    cudaGetSymbolAddress((void**)&T,    g_T);
    cudaGetSymbolAddress((void**)&z2,   g_z2);
    cudaGetSymbolAddress((void**)&x1h,  g_x1h);  cudaGetSymbolAddress((void**)&x1l, g_x1l);
    cudaGetSymbolAddress((void**)&x2h,  g_x2h);  cudaGetSymbolAddress((void**)&x2l, g_x2l);
    cudaGetSymbolAddress((void**)&Rh,   g_Rh);   cudaGetSymbolAddress((void**)&Rl,  g_Rl);
    cudaGetSymbolAddress((void**)&z1h,  g_z1h);  cudaGetSymbolAddress((void**)&z1l, g_z1l);
    cudaGetSymbolAddress((void**)&bW1h, g_bW1h); cudaGetSymbolAddress((void**)&bW1l, g_bW1l);
    cudaGetSymbolAddress((void**)&bW2h, g_bW2h); cudaGetSymbolAddress((void**)&bW2l, g_bW2l);
    cudaGetSymbolAddress((void**)&tW0h, g_tW0h); cudaGetSymbolAddress((void**)&tW0l, g_tW0l);
    cudaGetSymbolAddress((void**)&tW1h, g_tW1h); cudaGetSymbolAddress((void**)&tW1l, g_tW1l);

    const int SMEM = 2 * 49152;  // 96KB double-buffered stage
    cudaFuncSetAttribute(gemm_mma, cudaFuncAttributeMaxDynamicSharedMemorySize, SMEM);

    detect_idx_kernel<<<1, 32>>>((const int*)lsi);

    // weight split (+ pad for top_W0: 415 -> 448)
    padsplit_kernel<<<(256 * 512 + 255) / 256, 256>>>(bW1, bW1h, bW1l, 256, 512, 512);
    padsplit_kernel<<<(64 * 256 + 255) / 256, 256>>>(bW2, bW2h, bW2l, 64, 256, 256);
    padsplit_kernel<<<(512 * 448 + 255) / 256, 256>>>(tW0, tW0h, tW0l, 512, 415, 448);
    padsplit_kernel<<<(256 * 512 + 255) / 256, 256>>>(tW1, tW1h, tW1l, 256, 512, 512);

    // bottom MLP
    bot0_kernel<<<B_SZ / 16, 256>>>(dense_x, bW0, bb0, x1h, x1l);
    gemm_mma<<<dim3(4, 128), 256, SMEM>>>(x1h, x1l, bW1h, bW1l, bb1, 512, 8,
                                          nullptr, x2h, x2l, 256, 1, 1);
    gemm_mma<<<dim3(1, 128), 256, SMEM>>>(x2h, x2l, bW2h, bW2l, bb2, 256, 4,
                                          T, nullptr, nullptr, 1728, 1, 0);

    // embedding gather-sum into Tmat rows 1..26
    gather_kernel<<<(NTAB * B_SZ) / 8, 256>>>(emb, lsi, T);

    // interaction -> split R[B,448]
    interact_kernel<<<B_SZ, 128>>>(T, Rh, Rl);

    // top MLP
    gemm_mma<<<dim3(8, 128), 256, SMEM>>>(Rh, Rl, tW0h, tW0l, tb0, 448, 7,
                                          nullptr, z1h, z1l, 512, 1, 1);
    gemm_mma<<<dim3(4, 128), 256, SMEM>>>(z1h, z1l, tW1h, tW1l, tb1, 512, 8,
                                          z2, nullptr, nullptr, 256, 1, 0);
    top_final_kernel<<<B_SZ / 8, 256>>>(z2, tW2, tb2, (float*)d_out);
}

// round 6
// speedup vs baseline: 2.3276x; 1.2583x over previous
#include <cuda_runtime.h>
#include <cuda_bf16.h>
#include <math.h>
#include <stdint.h>

#define B_SZ   16384
#define NTAB   26
#define VOCAB  100000
#define EMB_D  64

// ======================= scratch (device globals) ==========================
__device__ __align__(256) float g_x [B_SZ * 64];            // bot MLP out fp32
__device__ __align__(256) float g_z2[B_SZ * 256];           // top L1 out fp32

__device__ __align__(256) __nv_bfloat16 g_x1h[B_SZ * 512];
__device__ __align__(256) __nv_bfloat16 g_x1l[B_SZ * 512];
__device__ __align__(256) __nv_bfloat16 g_x2h[B_SZ * 256];
__device__ __align__(256) __nv_bfloat16 g_x2l[B_SZ * 256];
__device__ __align__(256) __nv_bfloat16 g_Rh [B_SZ * 448];
__device__ __align__(256) __nv_bfloat16 g_Rl [B_SZ * 448];
__device__ __align__(256) __nv_bfloat16 g_z1h[B_SZ * 512];
__device__ __align__(256) __nv_bfloat16 g_z1l[B_SZ * 512];

__device__ __align__(256) __nv_bfloat16 g_bW1h[256 * 512];
__device__ __align__(256) __nv_bfloat16 g_bW1l[256 * 512];
__device__ __align__(256) __nv_bfloat16 g_bW2h[64 * 256];
__device__ __align__(256) __nv_bfloat16 g_bW2l[64 * 256];
__device__ __align__(256) __nv_bfloat16 g_tW0h[512 * 448];
__device__ __align__(256) __nv_bfloat16 g_tW0l[512 * 448];
__device__ __align__(256) __nv_bfloat16 g_tW1h[256 * 512];
__device__ __align__(256) __nv_bfloat16 g_tW1l[256 * 512];

__device__ int g_idx_is64;

// ======================= helpers ============================================
__device__ __forceinline__ uint32_t smem_u32(const void* p) {
    uint32_t a;
    asm("{ .reg .u64 t; cvta.to.shared.u64 t, %1; cvt.u32.u64 %0, t; }"
        : "=r"(a) : "l"(p));
    return a;
}
__device__ __forceinline__ void cpa16(uint32_t saddr, const void* g) {
    asm volatile("cp.async.cg.shared.global [%0], [%1], 16;" :: "r"(saddr), "l"(g));
}
__device__ __forceinline__ void cpa_commit() {
    asm volatile("cp.async.commit_group;" ::: "memory");
}
__device__ __forceinline__ void cpa_wait1() {
    asm volatile("cp.async.wait_group 1;" ::: "memory");
}
__device__ __forceinline__ void cpa_wait0() {
    asm volatile("cp.async.wait_group 0;" ::: "memory");
}
__device__ __forceinline__ void ldm_x4(uint32_t a, uint32_t& r0, uint32_t& r1,
                                       uint32_t& r2, uint32_t& r3) {
    asm volatile("ldmatrix.sync.aligned.m8n8.x4.shared.b16 {%0,%1,%2,%3}, [%4];"
                 : "=r"(r0), "=r"(r1), "=r"(r2), "=r"(r3) : "r"(a));
}
__device__ __forceinline__ void mma16816(float* c, const uint32_t* a,
                                         const uint32_t* b) {
    asm volatile(
        "mma.sync.aligned.m16n8k16.row.col.f32.bf16.bf16.f32 "
        "{%0,%1,%2,%3}, {%4,%5,%6,%7}, {%8,%9}, {%0,%1,%2,%3};"
        : "+f"(c[0]), "+f"(c[1]), "+f"(c[2]), "+f"(c[3])
        : "r"(a[0]), "r"(a[1]), "r"(a[2]), "r"(a[3]), "r"(b[0]), "r"(b[1]));
}
__device__ __forceinline__ void split_f32(float v, __nv_bfloat16& h, __nv_bfloat16& l) {
    h = __float2bfloat16(v);
    l = __float2bfloat16(v - __bfloat162float(h));
}

// ======================= index dtype detect =================================
__global__ void detect_idx_kernel(const int* __restrict__ lsi32) {
    int any = 0;
    for (int k = threadIdx.x; k < 2048; k += 32)
        if (lsi32[2 * k + 1] != 0) any = 1;
    any = __any_sync(0xFFFFFFFFu, any);
    if (threadIdx.x == 0) g_idx_is64 = any ? 0 : 1;
}

// ======================= weight pad + split =================================
__global__ void padsplit_kernel(const float* __restrict__ W,
                                __nv_bfloat16* __restrict__ Wh,
                                __nv_bfloat16* __restrict__ Wl,
                                int N, int Kin, int Kpad) {
    const int i = blockIdx.x * 256 + threadIdx.x;
    if (i >= N * Kpad) return;
    const int n = i / Kpad;
    const int k = i - n * Kpad;
    const float v = (k < Kin) ? W[n * Kin + k] : 0.f;
    __nv_bfloat16 h, l; split_f32(v, h, l);
    Wh[i] = h; Wl[i] = l;
}

// ======================= bot layer 0 (K=13) -> split out ====================
__global__ void __launch_bounds__(256) bot0_kernel(
    const float* __restrict__ X, const float* __restrict__ W,
    const float* __restrict__ bias,
    __nv_bfloat16* __restrict__ Yh, __nv_bfloat16* __restrict__ Yl)
{
    __shared__ float sW[512 * 13];
    __shared__ float sb[512];
    __shared__ float sx[16 * 13];
    const int tid = threadIdx.x;
    const int r0 = blockIdx.x * 16;
    for (int i = tid; i < 512 * 13; i += 256) sW[i] = W[i];
    for (int i = tid; i < 512; i += 256) sb[i] = bias[i];
    for (int i = tid; i < 16 * 13; i += 256) sx[i] = X[r0 * 13 + i];
    __syncthreads();
    for (int o = tid; o < 16 * 512; o += 256) {
        const int r = o >> 9;
        const int c = o & 511;
        float acc = sb[c];
        #pragma unroll
        for (int k = 0; k < 13; k++) acc += sx[r * 13 + k] * sW[c * 13 + k];
        acc = fmaxf(acc, 0.f);
        __nv_bfloat16 h, l; split_f32(acc, h, l);
        const size_t idx = (size_t)(r0 + r) * 512 + c;
        Yh[idx] = h; Yl[idx] = l;
    }
}

// ======================= mma.sync bf16x3 GEMM ===============================
#define STG 49152u
__device__ __forceinline__ uint32_t swz(int row, int chunk) {
    return (uint32_t)(row * 128 + ((chunk ^ (row & 7)) * 16));
}

__global__ void __launch_bounds__(256) gemm_mma(
    const __nv_bfloat16* __restrict__ Ah, const __nv_bfloat16* __restrict__ Al,
    const __nv_bfloat16* __restrict__ Wh, const __nv_bfloat16* __restrict__ Wl,
    const float* __restrict__ bias, int K, int NC,
    float* __restrict__ Cf,
    __nv_bfloat16* __restrict__ Ch, __nv_bfloat16* __restrict__ Cl,
    int ldc, int relu, int splitOut)
{
    extern __shared__ char smem[];
    const uint32_t sb = smem_u32(smem);
    const int tid  = threadIdx.x;
    const int lane = tid & 31;
    const int wid  = tid >> 5;
    const int wm   = wid >> 1;
    const int wn   = wid & 1;
    const int m0 = blockIdx.y * 128;
    const int n0 = blockIdx.x * 64;
    const size_t rowB = (size_t)K * 2;

    const char* gAh = (const char*)Ah + (size_t)m0 * rowB;
    const char* gAl = (const char*)Al + (size_t)m0 * rowB;
    const char* gWh = (const char*)Wh + (size_t)n0 * rowB;
    const char* gWl = (const char*)Wl + (size_t)n0 * rowB;

    float acc[2][4][4];
    #pragma unroll
    for (int t = 0; t < 2; t++)
        #pragma unroll
        for (int u = 0; u < 4; u++)
            #pragma unroll
            for (int v = 0; v < 4; v++) acc[t][u][v] = 0.f;

    auto load_stage = [&](int c) {
        const uint32_t so = sb + (uint32_t)(c & 1) * STG;
        const size_t kb = (size_t)c * 128;
        #pragma unroll
        for (int i = 0; i < 4; i++) {
            const int e = tid + i * 256;
            const int row = e >> 3;
            const int ch  = e & 7;
            const size_t gs = (size_t)row * rowB + kb + ch * 16;
            const uint32_t d = swz(row, ch);
            cpa16(so + d,          gAh + gs);
            cpa16(so + 16384 + d,  gAl + gs);
        }
        #pragma unroll
        for (int i = 0; i < 2; i++) {
            const int e = tid + i * 256;
            const int row = e >> 3;
            const int ch  = e & 7;
            const size_t gs = (size_t)row * rowB + kb + ch * 16;
            const uint32_t d = swz(row, ch);
            cpa16(so + 32768 + d, gWh + gs);
            cpa16(so + 40960 + d, gWl + gs);
        }
        cpa_commit();
    };

    load_stage(0);
    for (int c = 0; c < NC; ++c) {
        if (c + 1 < NC) load_stage(c + 1);
        if (c + 1 < NC) cpa_wait1(); else cpa_wait0();
        __syncthreads();

        const uint32_t so = sb + (uint32_t)(c & 1) * STG;
        const uint32_t sAhB = so, sAlB = so + 16384;
        const uint32_t sWhB = so + 32768, sWlB = so + 40960;

        #pragma unroll
        for (int kk = 0; kk < 4; kk++) {
            uint32_t ah[2][4], al[2][4], bh[8], bl[8];
            #pragma unroll
            for (int t = 0; t < 2; t++) {
                const int row = wm * 32 + t * 16 + (lane & 15);
                const int ch  = kk * 2 + (lane >> 4);
                const uint32_t d = swz(row, ch);
                ldm_x4(sAhB + d, ah[t][0], ah[t][1], ah[t][2], ah[t][3]);
                ldm_x4(sAlB + d, al[t][0], al[t][1], al[t][2], al[t][3]);
            }
            #pragma unroll
            for (int p = 0; p < 2; p++) {
                const int row = wn * 32 + p * 16 + ((lane >> 4) & 1) * 8 + (lane & 7);
                const int ch  = kk * 2 + ((lane >> 3) & 1);
                const uint32_t d = swz(row, ch);
                ldm_x4(sWhB + d, bh[p * 4 + 0], bh[p * 4 + 1], bh[p * 4 + 2], bh[p * 4 + 3]);
                ldm_x4(sWlB + d, bl[p * 4 + 0], bl[p * 4 + 1], bl[p * 4 + 2], bl[p * 4 + 3]);
            }
            #pragma unroll
            for (int t = 0; t < 2; t++)
                #pragma unroll
                for (int u = 0; u < 4; u++) {
                    mma16816(acc[t][u], ah[t], &bh[u * 2]);
                    mma16816(acc[t][u], ah[t], &bl[u * 2]);
                    mma16816(acc[t][u], al[t], &bh[u * 2]);
                }
        }
        __syncthreads();
    }

    #pragma unroll
    for (int t = 0; t < 2; t++) {
        const int rbase = m0 + wm * 32 + t * 16 + (lane >> 2);
        #pragma unroll
        for (int u = 0; u < 4; u++) {
            const int gn = n0 + wn * 32 + u * 8 + (lane & 3) * 2;
            const float b0 = __ldg(&bias[gn]);
            const float b1 = __ldg(&bias[gn + 1]);
            #pragma unroll
            for (int h = 0; h < 2; h++) {
                float v0 = acc[t][u][h * 2 + 0] + b0;
                float v1 = acc[t][u][h * 2 + 1] + b1;
                if (relu) { v0 = fmaxf(v0, 0.f); v1 = fmaxf(v1, 0.f); }
                const size_t idx = (size_t)(rbase + h * 8) * ldc + gn;
                if (splitOut) {
                    __nv_bfloat16 h0, l0, h1, l1;
                    split_f32(v0, h0, l0); split_f32(v1, h1, l1);
                    *reinterpret_cast<__nv_bfloat162*>(Ch + idx) = __halves2bfloat162(h0, h1);
                    *reinterpret_cast<__nv_bfloat162*>(Cl + idx) = __halves2bfloat162(l0, l1);
                } else {
                    *reinterpret_cast<float2*>(Cf + idx) = make_float2(v0, v1);
                }
            }
        }
    }
}

// ======== fused gather + interaction: one block per sample =================
__global__ void __launch_bounds__(128) gather_interact_kernel(
    const float* __restrict__ x, const float* __restrict__ emb,
    const void* __restrict__ lsi,
    __nv_bfloat16* __restrict__ Rh, __nv_bfloat16* __restrict__ Rl)
{
    __shared__ float s[27][65];
    const int b   = blockIdx.x;
    const int tid = threadIdx.x;
    const int wid = tid >> 5;
    const int lane = tid & 31;
    const int is64 = g_idx_is64;
    const long long* ip64 = (const long long*)lsi;
    const int*       ip32 = (const int*)lsi;

    // x row -> s[0]
    if (tid < 32) {
        float2 v = *reinterpret_cast<const float2*>(x + (size_t)b * 64 + tid * 2);
        s[0][tid * 2] = v.x; s[0][tid * 2 + 1] = v.y;
    }
    // embedding gather-sum: warp w handles tables w, w+4, ...
    for (int t = wid; t < NTAB; t += 4) {
        const size_t base = ((size_t)t * B_SZ + b) * 4;
        float2 acc = make_float2(0.f, 0.f);
        #pragma unroll
        for (int l = 0; l < 4; l++) {
            long long ix = is64 ? ip64[base + l] : (long long)ip32[base + l];
            if (ix < 0) ix = 0;
            if (ix >= VOCAB) ix = VOCAB - 1;
            const float2* row = reinterpret_cast<const float2*>(
                emb + ((size_t)t * VOCAB + (size_t)ix) * EMB_D);
            float2 v = __ldg(&row[lane]);
            acc.x += v.x; acc.y += v.y;
        }
        s[1 + t][lane * 2] = acc.x; s[1 + t][lane * 2 + 1] = acc.y;
    }
    __syncthreads();

    __nv_bfloat16* Rbh = Rh + (size_t)b * 448;
    __nv_bfloat16* Rbl = Rl + (size_t)b * 448;

    if (tid < 64) {
        __nv_bfloat16 h, l; split_f32(s[0][tid], h, l);
        Rbh[tid] = h; Rbl[tid] = l;
    }
    for (int c = 415 + tid; c < 448; c += 128) {
        Rbh[c] = __float2bfloat16(0.f); Rbl[c] = __float2bfloat16(0.f);
    }

    // 2x2 pair tiles over the 27x27 lower triangle: 105 tiles (ti>=tj, 14x14)
    if (tid < 105) {
        int ti = (int)(0.5f * (sqrtf(8.0f * (float)tid + 1.0f) - 1.0f));
        while (ti * (ti + 1) / 2 > tid) --ti;
        while ((ti + 1) * (ti + 2) / 2 <= tid) ++ti;
        const int tj = tid - ti * (ti + 1) / 2;
        const int i0 = 2 * ti, i1 = 2 * ti + 1;
        const int j0 = 2 * tj, j1 = 2 * tj + 1;
        const float* si0 = s[i0];
        const float* si1 = s[(i1 < 27) ? i1 : 26];   // clamp (values unused when OOB)
        const float* sj0 = s[j0];
        const float* sj1 = s[(j1 < 27) ? j1 : 26];   // clamp (values unused when OOB)
        float d00 = 0.f, d01 = 0.f, d10 = 0.f, d11 = 0.f;
        #pragma unroll
        for (int k = 0; k < 64; k++) {
            const float a0 = si0[k], a1 = si1[k];
            const float b0 = sj0[k], b1 = sj1[k];
            d00 += a0 * b0; d01 += a0 * b1;
            d10 += a1 * b0; d11 += a1 * b1;
        }
        __nv_bfloat16 h, l;
        const bool offd = (ti > tj);
        const bool row1 = (i1 < 27);
        if (offd) {
            split_f32(d00, h, l);
            { const int p = i0 * (i0 - 1) / 2 + j0; Rbh[64 + p] = h; Rbl[64 + p] = l; }
            split_f32(d01, h, l);
            { const int p = i0 * (i0 - 1) / 2 + j1; Rbh[64 + p] = h; Rbl[64 + p] = l; }
        }
        if (row1) {
            split_f32(d10, h, l);
            { const int p = i1 * (i1 - 1) / 2 + j0; Rbh[64 + p] = h; Rbl[64 + p] = l; }
            if (offd) {
                split_f32(d11, h, l);
                { const int p = i1 * (i1 - 1) / 2 + j1; Rbh[64 + p] = h; Rbl[64 + p] = l; }
            }
        }
    }
}

// ======================= final layer + sigmoid ==============================
__global__ void __launch_bounds__(256) top_final_kernel(
    const float* __restrict__ Z, const float* __restrict__ W,
    const float* __restrict__ bias, float* __restrict__ out)
{
    const int b = blockIdx.x * 8 + (threadIdx.x >> 5);
    const int lane = threadIdx.x & 31;
    const float* zr = Z + (size_t)b * 256;
    float acc = 0.f;
    #pragma unroll
    for (int k = lane; k < 256; k += 32) acc += zr[k] * W[k];
    #pragma unroll
    for (int off = 16; off > 0; off >>= 1)
        acc += __shfl_xor_sync(0xFFFFFFFFu, acc, off);
    if (lane == 0) {
        const float v = acc + bias[0];
        out[b] = 1.f / (1.f + expf(-v));
    }
}

// ======================= launch =============================================
extern "C" void kernel_launch(void* const* d_in, const int* in_sizes, int n_in,
                              void* d_out, int out_size)
{
    (void)n_in; (void)out_size;
    const float* dense_x = (const float*)d_in[0];
    const void*  lsi     = d_in[2];
    const float* emb     = (const float*)d_in[3];

    const float *bW0, *bb0, *bW1, *bb1, *bW2, *bb2;
    const float *tW0, *tb0, *tW1, *tb1, *tW2, *tb2;
    if (in_sizes[6] == 512 * 415) {
        bW0 = (const float*)d_in[4];  bb0 = (const float*)d_in[5];
        tW0 = (const float*)d_in[6];  tb0 = (const float*)d_in[7];
        bW1 = (const float*)d_in[8];  bb1 = (const float*)d_in[9];
        tW1 = (const float*)d_in[10]; tb1 = (const float*)d_in[11];
        bW2 = (const float*)d_in[12]; bb2 = (const float*)d_in[13];
        tW2 = (const float*)d_in[14]; tb2 = (const float*)d_in[15];
    } else {
        bW0 = (const float*)d_in[4];  bb0 = (const float*)d_in[5];
        bW1 = (const float*)d_in[6];  bb1 = (const float*)d_in[7];
        bW2 = (const float*)d_in[8];  bb2 = (const float*)d_in[9];
        tW0 = (const float*)d_in[10]; tb0 = (const float*)d_in[11];
        tW1 = (const float*)d_in[12]; tb1 = (const float*)d_in[13];
        tW2 = (const float*)d_in[14]; tb2 = (const float*)d_in[15];
    }

    float *x, *z2;
    __nv_bfloat16 *x1h, *x1l, *x2h, *x2l, *Rh, *Rl, *z1h, *z1l;
    __nv_bfloat16 *bW1h, *bW1l, *bW2h, *bW2l, *tW0h, *tW0l, *tW1h, *tW1l;
    cudaGetSymbolAddress((void**)&x,    g_x);
    cudaGetSymbolAddress((void**)&z2,   g_z2);
    cudaGetSymbolAddress((void**)&x1h,  g_x1h);  cudaGetSymbolAddress((void**)&x1l, g_x1l);
    cudaGetSymbolAddress((void**)&x2h,  g_x2h);  cudaGetSymbolAddress((void**)&x2l, g_x2l);
    cudaGetSymbolAddress((void**)&Rh,   g_Rh);   cudaGetSymbolAddress((void**)&Rl,  g_Rl);
    cudaGetSymbolAddress((void**)&z1h,  g_z1h);  cudaGetSymbolAddress((void**)&z1l, g_z1l);
    cudaGetSymbolAddress((void**)&bW1h, g_bW1h); cudaGetSymbolAddress((void**)&bW1l, g_bW1l);
    cudaGetSymbolAddress((void**)&bW2h, g_bW2h); cudaGetSymbolAddress((void**)&bW2l, g_bW2l);
    cudaGetSymbolAddress((void**)&tW0h, g_tW0h); cudaGetSymbolAddress((void**)&tW0l, g_tW0l);
    cudaGetSymbolAddress((void**)&tW1h, g_tW1h); cudaGetSymbolAddress((void**)&tW1l, g_tW1l);

    const int SMEM = 2 * 49152;
    cudaFuncSetAttribute(gemm_mma, cudaFuncAttributeMaxDynamicSharedMemorySize, SMEM);

    detect_idx_kernel<<<1, 32>>>((const int*)lsi);

    padsplit_kernel<<<(256 * 512 + 255) / 256, 256>>>(bW1, bW1h, bW1l, 256, 512, 512);
    padsplit_kernel<<<(64 * 256 + 255) / 256, 256>>>(bW2, bW2h, bW2l, 64, 256, 256);
    padsplit_kernel<<<(512 * 448 + 255) / 256, 256>>>(tW0, tW0h, tW0l, 512, 415, 448);
    padsplit_kernel<<<(256 * 512 + 255) / 256, 256>>>(tW1, tW1h, tW1l, 256, 512, 512);

    // bottom MLP -> compact x[B,64]
    bot0_kernel<<<B_SZ / 16, 256>>>(dense_x, bW0, bb0, x1h, x1l);
    gemm_mma<<<dim3(4, 128), 256, SMEM>>>(x1h, x1l, bW1h, bW1l, bb1, 512, 8,
                                          nullptr, x2h, x2l, 256, 1, 1);
    gemm_mma<<<dim3(1, 128), 256, SMEM>>>(x2h, x2l, bW2h, bW2l, bb2, 256, 4,
                                          x, nullptr, nullptr, 64, 1, 0);

    // fused gather + interaction -> split R[B,448]
    gather_interact_kernel<<<B_SZ, 128>>>(x, emb, lsi, Rh, Rl);

    // top MLP
    gemm_mma<<<dim3(8, 128), 256, SMEM>>>(Rh, Rl, tW0h, tW0l, tb0, 448, 7,
                                          nullptr, z1h, z1l, 512, 1, 1);
    gemm_mma<<<dim3(4, 128), 256, SMEM>>>(z1h, z1l, tW1h, tW1l, tb1, 512, 8,
                                          z2, nullptr, nullptr, 256, 1, 0);
    top_final_kernel<<<B_SZ / 8, 256>>>(z2, tW2, tb2, (float*)d_out);
}